// round 1
// baseline (speedup 1.0000x reference)
#include <cuda_runtime.h>
#include <math.h>

// ---------------- problem constants ----------------
#define Bc    16
#define TZc   2048
#define TTc   512
#define Dc    256
#define DFFc  1024
#define Lc    6
#define Hc    4
#define DHc   64
#define CHc   256
#define HIDc  256
#define KTAP  5
#define FLOWSc 4
#define Gc    256
#define NEGF  (-1000000000.0f)

// ---------------- scratch (device globals; no allocations) ----------------
__device__ float g_h  [Bc*TTc*Dc];
__device__ float g_q  [Bc*TTc*Dc];
__device__ float g_k  [Bc*TTc*Dc];
__device__ float g_v  [Bc*TTc*Dc];
__device__ float g_ao [Bc*TTc*Dc];
__device__ float g_t1 [Bc*TTc*Dc];
__device__ float g_ffn[Bc*TTc*DFFc];
__device__ float g_sc [Bc*Hc*TTc*TTc];
__device__ float g_mu [Bc*TTc*Dc];
__device__ float g_lv [Bc*TTc*Dc];
__device__ float g_wext[Bc*TTc*2*Dc];
__device__ float g_cb [Bc*TTc];
__device__ float g_zca[Bc*TZc*CHc];
__device__ float g_zcb[Bc*TZc*CHc];
__device__ float g_hh [Bc*TZc*HIDc];
__device__ float g_hh2[Bc*TZc*HIDc];
__device__ float g_m  [Bc*TZc*(CHc/2)];
__device__ float g_cp [Bc*HIDc];
__device__ float g_xe [Bc*TZc*2*CHc];
__device__ float g_logp[(size_t)Bc*TZc*TTc];
__device__ unsigned char g_ch[(size_t)Bc*(TZc-1)*TTc];
__device__ int   g_path[Bc*TZc];

// ---------------- reductions ----------------
__device__ __forceinline__ float warpSum(float v){
  #pragma unroll
  for (int o=16;o;o>>=1) v += __shfl_xor_sync(0xffffffffu, v, o);
  return v;
}
__device__ __forceinline__ float warpMax(float v){
  #pragma unroll
  for (int o=16;o;o>>=1) v = fmaxf(v, __shfl_xor_sync(0xffffffffu, v, o));
  return v;
}

// ---------------- generic batched GEMM: C = A @ B (+bias, +group-bias, act, mask) ----------------
struct GemmP {
  const float* A; int lda; long long sAo, sAi; int icA;
  const float* Bm; int ldb; long long sBo, sBi; int icB;
  float* C; int ldc; long long sCo, sCi; int icC;
  const float* bias; long long biasStride;   // bias[z*biasStride + n]
  const float* rg; int rpg;                  // rg[(m/rpg)*N + n]
  const int* mask; int maskN;                // mask[z*maskN + n]==0 -> NEGF
  int M, N, K, act;                          // act: 0 none, 1 relu, 2 tanh
};

template<int TB>
__global__ __launch_bounds__(256) void gemm_kernel(GemmP p){
  __shared__ float As[16][68], Bs[16][68];
  int z = blockIdx.z;
  const float* A  = p.A  + (long long)(z/p.icA)*p.sAo + (long long)(z%p.icA)*p.sAi;
  const float* Bm = p.Bm + (long long)(z/p.icB)*p.sBo + (long long)(z%p.icB)*p.sBi;
  float* C        = p.C  + (long long)(z/p.icC)*p.sCo + (long long)(z%p.icC)*p.sCi;
  int m0 = blockIdx.y*64, n0 = blockIdx.x*64;
  int tid = threadIdx.x, tx = tid&15, ty = tid>>4;
  float acc[4][4] = {};
  for (int k0=0;k0<p.K;k0+=16){
    #pragma unroll
    for (int i=0;i<4;i++){
      int idx = tid + i*256; int r = idx>>4, c = idx&15;
      int gm = m0+r, gk = k0+c;
      As[c][r] = (gm<p.M && gk<p.K) ? A[(long long)gm*p.lda + gk] : 0.f;
    }
    #pragma unroll
    for (int i=0;i<4;i++){
      int idx = tid + i*256;
      if (TB){
        int n = idx>>4, c = idx&15; int gn=n0+n, gk=k0+c;
        Bs[c][n] = (gn<p.N && gk<p.K) ? Bm[(long long)gn*p.ldb + gk] : 0.f;
      } else {
        int c = idx>>6, n = idx&63; int gn=n0+n, gk=k0+c;
        Bs[c][n] = (gn<p.N && gk<p.K) ? Bm[(long long)gk*p.ldb + gn] : 0.f;
      }
    }
    __syncthreads();
    #pragma unroll
    for (int k=0;k<16;k++){
      float av[4], bv[4];
      #pragma unroll
      for (int i=0;i<4;i++) av[i] = As[k][ty + 16*i];
      #pragma unroll
      for (int j=0;j<4;j++) bv[j] = Bs[k][tx + 16*j];
      #pragma unroll
      for (int i=0;i<4;i++)
        #pragma unroll
        for (int j=0;j<4;j++) acc[i][j] = fmaf(av[i], bv[j], acc[i][j]);
    }
    __syncthreads();
  }
  #pragma unroll
  for (int i=0;i<4;i++){
    int gm = m0 + ty + 16*i; if (gm >= p.M) continue;
    #pragma unroll
    for (int j=0;j<4;j++){
      int gn = n0 + tx + 16*j; if (gn >= p.N) continue;
      float v = acc[i][j];
      if (p.bias) v += p.bias[(long long)z*p.biasStride + gn];
      if (p.rg)   v += p.rg[(long long)(gm/p.rpg)*p.N + gn];
      if (p.act==1) v = fmaxf(v, 0.f);
      else if (p.act==2) v = tanhf(v);
      if (p.mask && p.mask[(long long)z*p.maskN + gn]==0) v = NEGF;
      C[(long long)gm*p.ldc + gn] = v;
    }
  }
}

// ---------------- depthwise-free 1D conv as GEMM (K = 5*256, zero-pad per batch) ----------------
__global__ __launch_bounds__(256) void conv_kernel(const float* __restrict__ X,
                                                   const float* __restrict__ W,
                                                   const float* __restrict__ bias,
                                                   float* __restrict__ Y){
  __shared__ float As[16][68], Bs[16][68];
  int m0 = blockIdx.y*64, n0 = blockIdx.x*64;
  int tid = threadIdx.x, tx = tid&15, ty = tid>>4;
  float acc[4][4] = {};
  for (int k0=0;k0<KTAP*HIDc;k0+=16){
    #pragma unroll
    for (int i=0;i<4;i++){
      int idx = tid + i*256; int r = idx>>4, c = idx&15;
      int kk = k0 + c; int tap = kk>>8; int ci = kk&255;
      int gm = m0 + r; int b = gm>>11; int t = (gm&2047) + tap - 2;
      As[c][r] = (t>=0 && t<TZc) ? X[(((size_t)b<<11)+t)*HIDc + ci] : 0.f;
    }
    #pragma unroll
    for (int i=0;i<4;i++){
      int idx = tid + i*256; int c = idx>>6, n = idx&63;
      Bs[c][n] = W[(size_t)(k0+c)*HIDc + n0 + n];
    }
    __syncthreads();
    #pragma unroll
    for (int k=0;k<16;k++){
      float av[4], bv[4];
      #pragma unroll
      for (int i=0;i<4;i++) av[i] = As[k][ty + 16*i];
      #pragma unroll
      for (int j=0;j<4;j++) bv[j] = Bs[k][tx + 16*j];
      #pragma unroll
      for (int i=0;i<4;i++)
        #pragma unroll
        for (int j=0;j<4;j++) acc[i][j] = fmaf(av[i], bv[j], acc[i][j]);
    }
    __syncthreads();
  }
  #pragma unroll
  for (int i=0;i<4;i++){
    int gm = m0 + ty + 16*i;
    #pragma unroll
    for (int j=0;j<4;j++){
      int gn = n0 + tx + 16*j;
      Y[(size_t)gm*HIDc + gn] = tanhf(acc[i][j] + bias[gn]);
    }
  }
}

// ---------------- embedding + sinusoidal positions (double, matches numpy) ----------------
__global__ void embed_kernel(const int* __restrict__ text, const float* __restrict__ emb,
                             float* __restrict__ h){
  int row = blockIdx.x; int d = threadIdx.x;
  int t = row % TTc;
  int tok = text[row];
  double expo = (double)(2*(d/2)) / 256.0;
  double ang  = (double)t / pow(10000.0, expo);
  float pe = (float)(((d&1)==0) ? sin(ang) : cos(ang));
  h[(size_t)row*Dc + d] = emb[(size_t)tok*Dc + d] * 16.0f + pe;
}

// ---------------- residual + layernorm ----------------
__global__ void ln_kernel(const float* __restrict__ x, const float* __restrict__ add,
                          const float* __restrict__ g, const float* __restrict__ b,
                          float* __restrict__ out){
  int row = blockIdx.x; int d = threadIdx.x;      // 256 threads
  __shared__ float red[8];
  __shared__ float mean_s, var_s;
  float v = x[(size_t)row*Dc + d] + add[(size_t)row*Dc + d];
  float s = warpSum(v);
  if ((d&31)==0) red[d>>5] = s;
  __syncthreads();
  if (d==0){ float t=0; for (int i=0;i<8;i++) t += red[i]; mean_s = t*(1.f/Dc); }
  __syncthreads();
  float diff = v - mean_s;
  s = warpSum(diff*diff);
  if ((d&31)==0) red[d>>5] = s;
  __syncthreads();
  if (d==0){ float t=0; for (int i=0;i<8;i++) t += red[i]; var_s = t*(1.f/Dc); }
  __syncthreads();
  out[(size_t)row*Dc + d] = g[d]*diff*rsqrtf(var_s + 1e-6f) + b[d];
}

// ---------------- masked softmax over keys (scale 1/8 folded in) ----------------
__global__ void softmax_kernel(float* __restrict__ sc, const int* __restrict__ text){
  int row = blockIdx.x;                      // over B*H*TT
  int b = row / (Hc*TTc);
  float* p = sc + (size_t)row*TTc;
  int tid = threadIdx.x;                     // 128 threads
  __shared__ float red[4];
  __shared__ float mx_s, sum_s;
  float v[4];
  #pragma unroll
  for (int i=0;i<4;i++){
    int j = tid + i*128;
    float s = p[j]*0.125f;
    if (text[b*TTc + j] == 0) s += NEGF;
    v[i] = s;
  }
  float m = fmaxf(fmaxf(v[0],v[1]), fmaxf(v[2],v[3]));
  m = warpMax(m);
  if ((tid&31)==0) red[tid>>5] = m;
  __syncthreads();
  if (tid==0) mx_s = fmaxf(fmaxf(red[0],red[1]), fmaxf(red[2],red[3]));
  __syncthreads();
  float mx = mx_s, s = 0.f;
  #pragma unroll
  for (int i=0;i<4;i++){ v[i] = expf(v[i]-mx); s += v[i]; }
  s = warpSum(s);
  if ((tid&31)==0) red[tid>>5] = s;
  __syncthreads();
  if (tid==0) sum_s = red[0]+red[1]+red[2]+red[3];
  __syncthreads();
  float inv = 1.f/sum_s;
  #pragma unroll
  for (int i=0;i<4;i++) p[tid + i*128] = v[i]*inv;
}

// ---------------- wext / constant-term prep for logp ----------------
__global__ void prep_kernel(const float* __restrict__ mu, const float* __restrict__ lv,
                            float* __restrict__ wext, float* __restrict__ cb){
  int row = blockIdx.x; int d = threadIdx.x;    // 256 threads
  __shared__ float red[8];
  float l = lv[(size_t)row*Dc + d];
  float m = mu[(size_t)row*Dc + d];
  float spr = expf(-l);
  wext[(size_t)row*2*Dc + d]      = -0.5f*spr;
  wext[(size_t)row*2*Dc + Dc + d] = m*spr;
  float contrib = -0.5f*1.8378770664093453f - 0.5f*l - 0.5f*m*m*spr;
  float s = warpSum(contrib);
  if ((d&31)==0) red[d>>5] = s;
  __syncthreads();
  if (d==0){ float t=0; for (int i=0;i<8;i++) t += red[i]; cb[row] = t; }
}

// ---------------- [zc^2, zc] feature build ----------------
__global__ void xext_kernel(const float* __restrict__ zc, float* __restrict__ xe){
  size_t idx = (size_t)blockIdx.x*256 + threadIdx.x;   // over B*TZ*256
  size_t row = idx >> 8; int d = (int)(idx & 255);
  float z = zc[idx];
  xe[row*512 + d]       = z*z;
  xe[row*512 + 256 + d] = z;
}

// ---------------- flow coupling update ----------------
__global__ void flowupd_kernel(const float* __restrict__ src, const float* __restrict__ m,
                               float* __restrict__ dst){
  size_t idx = (size_t)blockIdx.x*128 + threadIdx.x;   // over B*TZ*128
  size_t row = idx >> 7; int c = (int)(idx & 127);
  dst[row*256 + c]       = src[row*256 + 128 + c] + m[row*128 + c];
  dst[row*256 + 128 + c] = src[row*256 + c];
}

// ---------------- MAS forward DP ----------------
__global__ void mas_fwd(const float* __restrict__ logp, unsigned char* __restrict__ ch){
  int b = blockIdx.x, j = threadIdx.x;            // 512 threads
  __shared__ float Q[2][TTc];
  const float* lp = logp + (size_t)b*TZc*TTc;
  Q[0][j] = (j==0) ? lp[j] : NEGF;
  __syncthreads();
  int cur = 0;
  float nxt = lp[TTc + j];
  for (int t=1; t<TZc; t++){
    float qj = Q[cur][j];
    float qm = (j>0) ? Q[cur][j-1] : NEGF;
    ch[((size_t)b*(TZc-1) + (t-1))*TTc + j] = (qm > qj) ? 1 : 0;
    float val = nxt + fmaxf(qj, qm);
    if (t+1 < TZc) nxt = lp[(size_t)(t+1)*TTc + j];
    Q[cur^1][j] = val;
    cur ^= 1;
    __syncthreads();
  }
}

// ---------------- MAS backtrack ----------------
__global__ void mas_bwd(const unsigned char* __restrict__ ch, const int* __restrict__ text,
                        int* __restrict__ path){
  int b = blockIdx.x; int tid = threadIdx.x;       // 512 threads
  __shared__ int red[16];
  int m = (text[b*TTc + tid] != 0) ? 1 : 0;
  #pragma unroll
  for (int o=16;o;o>>=1) m += __shfl_xor_sync(0xffffffffu, m, o);
  if ((tid&31)==0) red[tid>>5] = m;
  __syncthreads();
  if (tid==0){
    int s = 0; for (int i=0;i<16;i++) s += red[i];
    int j = s - 1;
    path[b*TZc + TZc-1] = j;
    const unsigned char* cb_ = ch + (size_t)b*(TZc-1)*TTc;
    for (int t=TZc-2; t>=0; t--){
      j -= (int)cb_[(size_t)t*TTc + j];
      path[b*TZc + t] = j;
    }
  }
}

// ---------------- outputs ----------------
__global__ void ctx_kernel(const float* __restrict__ mu, const int* __restrict__ path,
                           float* __restrict__ out){
  int row = blockIdx.x; int d = threadIdx.x;    // row over B*TZ
  int b = row / TZc;
  int j = path[row];
  out[(size_t)row*Dc + d] = mu[((size_t)b*TTc + j)*Dc + d];
}
__global__ void hcopy_kernel(const float* __restrict__ h, float* __restrict__ out){
  size_t idx = (size_t)blockIdx.x*256 + threadIdx.x;
  out[idx] = h[idx];
}

// ---------------- host orchestration ----------------
static void launch_gemm(const float*A,int lda,long long sAo,long long sAi,int icA,
                        const float*Bm,int ldb,long long sBo,long long sBi,int icB,int transB,
                        float*C,int ldc,long long sCo,long long sCi,int icC,
                        const float*bias,long long biasStride,
                        const float*rg,int rpg,
                        const int*mask,int maskN,
                        int M,int N,int K,int act,int batch)
{
  GemmP p;
  p.A=A; p.lda=lda; p.sAo=sAo; p.sAi=sAi; p.icA=icA;
  p.Bm=Bm; p.ldb=ldb; p.sBo=sBo; p.sBi=sBi; p.icB=icB;
  p.C=C; p.ldc=ldc; p.sCo=sCo; p.sCi=sCi; p.icC=icC;
  p.bias=bias; p.biasStride=biasStride; p.rg=rg; p.rpg=(rpg>0?rpg:1);
  p.mask=mask; p.maskN=maskN;
  p.M=M; p.N=N; p.K=K; p.act=act;
  dim3 grid((N+63)/64, (M+63)/64, batch);
  if (transB) gemm_kernel<1><<<grid,256>>>(p);
  else        gemm_kernel<0><<<grid,256>>>(p);
}

static void gemmS(const float*A,const float*Bm,const float*bias,float*C,int M,int N,int K,int act){
  launch_gemm(A,K,0,0,1, Bm,N,0,0,1, 0, C,N,0,0,1, bias,0, nullptr,1, nullptr,0, M,N,K,act,1);
}

extern "C" void kernel_launch(void* const* d_in, const int* in_sizes, int n_in,
                              void* d_out, int out_size){
  (void)in_sizes; (void)n_in; (void)out_size;
  const float* z     = (const float*)d_in[0];
  const int*   text  = (const int*)  d_in[1];
  const float* cond  = (const float*)d_in[2];
  const float* emb   = (const float*)d_in[3];
  const float* wq    = (const float*)d_in[4];
  const float* wk    = (const float*)d_in[5];
  const float* wv    = (const float*)d_in[6];
  const float* wo    = (const float*)d_in[7];
  const float* bq    = (const float*)d_in[8];
  const float* bk    = (const float*)d_in[9];
  const float* bv    = (const float*)d_in[10];
  const float* bo    = (const float*)d_in[11];
  const float* ln1g  = (const float*)d_in[12];
  const float* ln1b  = (const float*)d_in[13];
  const float* ln2g  = (const float*)d_in[14];
  const float* ln2b  = (const float*)d_in[15];
  const float* w1    = (const float*)d_in[16];
  const float* b1    = (const float*)d_in[17];
  const float* w2    = (const float*)d_in[18];
  const float* b2    = (const float*)d_in[19];
  const float* mu_w  = (const float*)d_in[20];
  const float* mu_b  = (const float*)d_in[21];
  const float* lv_w  = (const float*)d_in[22];
  const float* lv_b  = (const float*)d_in[23];
  const float* f_in  = (const float*)d_in[24];
  const float* f_inb = (const float*)d_in[25];
  const float* f_cd  = (const float*)d_in[26];
  const float* f_cv  = (const float*)d_in[27];
  const float* f_cvb = (const float*)d_in[28];
  const float* f_out = (const float*)d_in[29];
  const float* f_outb= (const float*)d_in[30];
  float* out = (float*)d_out;

  float *h,*q,*k,*v,*ao,*t1,*ffn,*sc,*mu,*lv,*wext,*cb,*zca,*zcb,*hh,*hh2,*mm,*cp,*xe,*lp;
  unsigned char* ch; int* path;
  cudaGetSymbolAddress((void**)&h,  g_h);
  cudaGetSymbolAddress((void**)&q,  g_q);
  cudaGetSymbolAddress((void**)&k,  g_k);
  cudaGetSymbolAddress((void**)&v,  g_v);
  cudaGetSymbolAddress((void**)&ao, g_ao);
  cudaGetSymbolAddress((void**)&t1, g_t1);
  cudaGetSymbolAddress((void**)&ffn,g_ffn);
  cudaGetSymbolAddress((void**)&sc, g_sc);
  cudaGetSymbolAddress((void**)&mu, g_mu);
  cudaGetSymbolAddress((void**)&lv, g_lv);
  cudaGetSymbolAddress((void**)&wext,g_wext);
  cudaGetSymbolAddress((void**)&cb, g_cb);
  cudaGetSymbolAddress((void**)&zca,g_zca);
  cudaGetSymbolAddress((void**)&zcb,g_zcb);
  cudaGetSymbolAddress((void**)&hh, g_hh);
  cudaGetSymbolAddress((void**)&hh2,g_hh2);
  cudaGetSymbolAddress((void**)&mm, g_m);
  cudaGetSymbolAddress((void**)&cp, g_cp);
  cudaGetSymbolAddress((void**)&xe, g_xe);
  cudaGetSymbolAddress((void**)&lp, g_logp);
  cudaGetSymbolAddress((void**)&ch, g_ch);
  cudaGetSymbolAddress((void**)&path, g_path);

  const int MROWS = Bc*TTc;           // 8192
  const int MZ    = Bc*TZc;           // 32768

  // ---- text encoder ----
  embed_kernel<<<MROWS, 256>>>(text, emb, h);
  for (int l=0; l<Lc; l++){
    const float* Wq = wq + (size_t)l*Dc*Dc;  const float* Bq = bq + (size_t)l*Dc;
    const float* Wk = wk + (size_t)l*Dc*Dc;  const float* Bk = bk + (size_t)l*Dc;
    const float* Wv = wv + (size_t)l*Dc*Dc;  const float* Bv = bv + (size_t)l*Dc;
    const float* Wo = wo + (size_t)l*Dc*Dc;  const float* Bo = bo + (size_t)l*Dc;
    gemmS(h, Wq, Bq, q, MROWS, Dc, Dc, 0);
    gemmS(h, Wk, Bk, k, MROWS, Dc, Dc, 0);
    gemmS(h, Wv, Bv, v, MROWS, Dc, Dc, 0);
    // scores[b,h] = q @ k^T   (batch 64 = b*H+h; head slice via inner offset 64)
    launch_gemm(q,Dc,(long long)TTc*Dc,DHc,Hc,
                k,Dc,(long long)TTc*Dc,DHc,Hc, 1,
                sc,TTc,(long long)TTc*TTc,0,1,
                nullptr,0, nullptr,0, nullptr,0,
                TTc,TTc,DHc,0, Bc*Hc);
    softmax_kernel<<<Bc*Hc*TTc, 128>>>(sc, text);
    // out[b,h] = attn @ v
    launch_gemm(sc,TTc,(long long)TTc*TTc,0,1,
                v,Dc,(long long)TTc*Dc,DHc,Hc, 0,
                ao,Dc,(long long)TTc*Dc,DHc,Hc,
                nullptr,0, nullptr,0, nullptr,0,
                TTc,DHc,TTc,0, Bc*Hc);
    gemmS(ao, Wo, Bo, t1, MROWS, Dc, Dc, 0);
    ln_kernel<<<MROWS, 256>>>(h, t1, ln1g + (size_t)l*Dc, ln1b + (size_t)l*Dc, h);
    gemmS(h, w1 + (size_t)l*Dc*DFFc, b1 + (size_t)l*DFFc, ffn, MROWS, DFFc, Dc, 1);
    gemmS(ffn, w2 + (size_t)l*DFFc*Dc, b2 + (size_t)l*Dc, t1, MROWS, Dc, DFFc, 0);
    ln_kernel<<<MROWS, 256>>>(h, t1, ln2g + (size_t)l*Dc, ln2b + (size_t)l*Dc, h);
  }

  // ---- mu / logvar / logp weights ----
  gemmS(h, mu_w, mu_b, mu, MROWS, Dc, Dc, 0);
  gemmS(h, lv_w, lv_b, lv, MROWS, Dc, Dc, 0);
  prep_kernel<<<MROWS, 256>>>(mu, lv, wext, cb);

  // ---- flows ----
  cudaMemcpyAsync(zca, z, (size_t)Bc*TZc*CHc*sizeof(float), cudaMemcpyDeviceToDevice);
  for (int f=0; f<FLOWSc; f++){
    float* src = (f&1) ? zcb : zca;
    float* dst = (f&1) ? zca : zcb;
    // cond projection (16 x 256)
    gemmS(cond, f_cd + (size_t)f*Gc*HIDc, nullptr, cp, Bc, HIDc, Gc, 0);
    // hh = x0 @ flow_in + b + condproj[b]
    launch_gemm(src,CHc,0,0,1,
                f_in + (size_t)f*(CHc/2)*HIDc, HIDc,0,0,1, 0,
                hh,HIDc,0,0,1,
                f_inb + (size_t)f*HIDc, 0,
                cp, TZc,
                nullptr,0,
                MZ, HIDc, CHc/2, 0, 1);
    // conv (K=5, SAME, per-batch zero pad) + tanh
    {
      dim3 grid((HIDc+63)/64, (MZ+63)/64, 1);
      conv_kernel<<<grid,256>>>(hh, f_cv + (size_t)f*KTAP*HIDc*HIDc,
                                f_cvb + (size_t)f*HIDc, hh2);
    }
    // m = hh2 @ flow_out + b
    gemmS(hh2, f_out + (size_t)f*HIDc*(CHc/2), f_outb + (size_t)f*(CHc/2),
          mm, MZ, CHc/2, HIDc, 0);
    // zc' = [x1 + m, x0]
    flowupd_kernel<<<(MZ*(CHc/2))/128, 128>>>(src, mm, dst);
  }
  // FLOWS=4 -> final zc in zca

  // ---- logp = [zc^2, zc] @ wext^T + c, masked ----
  xext_kernel<<<(MZ*CHc)/256, 256>>>(zca, xe);
  launch_gemm(xe,2*Dc,(long long)TZc*2*Dc,0,1,
              wext,2*Dc,(long long)TTc*2*Dc,0,1, 1,
              lp,TTc,(long long)TZc*TTc,0,1,
              cb, TTc,
              nullptr,0,
              text, TTc,
              TZc, TTc, 2*Dc, 0, Bc);

  // ---- MAS path + outputs ----
  mas_fwd<<<Bc, TTc>>>(lp, ch);
  mas_bwd<<<Bc, TTc>>>(ch, text, path);
  ctx_kernel<<<Bc*TZc, 256>>>(mu, path, out);
  hcopy_kernel<<<(Bc*TTc*Dc)/256, 256>>>(h, out + (size_t)Bc*TZc*Dc);
}

// round 17
// speedup vs baseline: 1.5653x; 1.5653x over previous
#include <cuda_runtime.h>
#include <math.h>

// ---------------- problem constants ----------------
#define Bc    16
#define TZc   2048
#define TTc   512
#define Dc    256
#define DFFc  1024
#define Lc    6
#define Hc    4
#define DHc   64
#define CHc   256
#define HIDc  256
#define KTAP  5
#define FLOWSc 4
#define Gc    256
#define NEGF  (-1000000000.0f)

// ---------------- scratch (device globals; no allocations) ----------------
__device__ float g_h  [Bc*TTc*Dc];
__device__ float g_q  [Bc*TTc*Dc];
__device__ float g_k  [Bc*TTc*Dc];
__device__ float g_v  [Bc*TTc*Dc];
__device__ float g_ao [Bc*TTc*Dc];
__device__ float g_t1 [Bc*TTc*Dc];
__device__ float g_ffn[Bc*TTc*DFFc];
__device__ float g_sc [Bc*Hc*TTc*TTc];
__device__ float g_mu [Bc*TTc*Dc];
__device__ float g_lv [Bc*TTc*Dc];
__device__ float g_wext[Bc*TTc*2*Dc];
__device__ float g_cb [Bc*TTc];
__device__ float g_zca[Bc*TZc*CHc];
__device__ float g_zcb[Bc*TZc*CHc];
__device__ float g_hh [Bc*TZc*HIDc];
__device__ float g_hh2[Bc*TZc*HIDc];
__device__ float g_m  [Bc*TZc*(CHc/2)];
__device__ float g_cp [Bc*HIDc];
__device__ float g_xe [Bc*TZc*2*CHc];
__device__ float g_pe [TTc*Dc];
__device__ float g_logp[(size_t)Bc*TZc*TTc];
__device__ unsigned int g_chp[(size_t)Bc*(TZc-1)*(TTc/32)];
__device__ int   g_path[Bc*TZc];

// ---------------- reductions ----------------
__device__ __forceinline__ float warpSum(float v){
  #pragma unroll
  for (int o=16;o;o>>=1) v += __shfl_xor_sync(0xffffffffu, v, o);
  return v;
}
__device__ __forceinline__ float warpMax(float v){
  #pragma unroll
  for (int o=16;o;o>>=1) v = fmaxf(v, __shfl_xor_sync(0xffffffffu, v, o));
  return v;
}

// ---------------- GEMM descriptor ----------------
struct GemmP {
  const float* A; int lda; long long sAo, sAi; int icA;
  const float* Bm; int ldb; long long sBo, sBi; int icB;
  float* C; int ldc; long long sCo, sCi; int icC;
  const float* bias; long long biasStride;   // bias[z*biasStride + n]
  const float* rg; int rpg;                  // rg[(m/rpg)*N + n]
  const int* mask; int maskN;                // mask[z*maskN + n]==0 -> NEGF
  int M, N, K, act;                          // act: 0 none, 1 relu, 2 tanh
};

// =====================================================================
// High-throughput SGEMM: 128x(128|64) block, 256 threads, 8x(8|4) microtile,
// double-buffered smem, 64 FFMA per 4 LDS.128 in the inner loop.
// Requires M%128==0, N%BNT==0, K%16==0 (all call sites satisfy this).
// CONVv: A is gathered from hh with 5-tap SAME conv addressing (stride 256).
// =====================================================================
template<int BNT, int TBv, int CONVv>
__global__ __launch_bounds__(256, 2) void sgemm_kernel(GemmP p){
  constexpr int NB   = (BNT==128) ? 8 : 4;
  constexpr int BSTR = BNT + 4;
  constexpr int NBF  = BNT/64;          // float4 loads per thread for B
  __shared__ float As[2][16][132];
  __shared__ float Bs[2][16][BSTR];
  const int z = blockIdx.z;
  const float* A  = p.A  + (long long)(z/p.icA)*p.sAo + (long long)(z%p.icA)*p.sAi;
  const float* Bm = p.Bm + (long long)(z/p.icB)*p.sBo + (long long)(z%p.icB)*p.sBi;
  float*       C  = p.C  + (long long)(z/p.icC)*p.sCo + (long long)(z%p.icC)*p.sCi;
  const int m0 = blockIdx.y*128, n0 = blockIdx.x*BNT;
  const int t = threadIdx.x, tx = t&15, ty = t>>4;

  float4 ra[2], rb[2];

  auto gload = [&](int k0){
    #pragma unroll
    for (int i=0;i<2;i++){
      int id = t + 256*i, am = id>>2, akq = id&3;
      if (CONVv){
        int gm = m0+am, tap = k0>>8, ci = (k0&255) + akq*4;
        int bb = gm>>11, tp = (gm&2047) + tap - 2;
        ra[i] = (tp>=0 && tp<TZc) ? *(const float4*)(A + ((size_t)((bb<<11)+tp))*256 + ci)
                                  : make_float4(0.f,0.f,0.f,0.f);
      } else {
        ra[i] = *(const float4*)(A + (size_t)(m0+am)*p.lda + k0 + akq*4);
      }
    }
    if (TBv){
      #pragma unroll
      for (int i=0;i<NBF;i++){
        int id = t + 256*i, bn = id>>2, bkq = id&3;
        rb[i] = *(const float4*)(Bm + (size_t)(n0+bn)*p.ldb + k0 + bkq*4);
      }
    } else {
      #pragma unroll
      for (int i=0;i<NBF;i++){
        int id = t + 256*i;
        int bk = id / (BNT/4), bnq = id % (BNT/4);
        rb[i] = *(const float4*)(Bm + (size_t)(k0+bk)*p.ldb + n0 + bnq*4);
      }
    }
  };
  auto sstore = [&](int buf){
    #pragma unroll
    for (int i=0;i<2;i++){
      int id = t + 256*i, am = id>>2, akq = id&3;
      As[buf][akq*4+0][am] = ra[i].x;
      As[buf][akq*4+1][am] = ra[i].y;
      As[buf][akq*4+2][am] = ra[i].z;
      As[buf][akq*4+3][am] = ra[i].w;
    }
    if (TBv){
      #pragma unroll
      for (int i=0;i<NBF;i++){
        int id = t + 256*i, bn = id>>2, bkq = id&3;
        Bs[buf][bkq*4+0][bn] = rb[i].x;
        Bs[buf][bkq*4+1][bn] = rb[i].y;
        Bs[buf][bkq*4+2][bn] = rb[i].z;
        Bs[buf][bkq*4+3][bn] = rb[i].w;
      }
    } else {
      #pragma unroll
      for (int i=0;i<NBF;i++){
        int id = t + 256*i;
        int bk = id / (BNT/4), bnq = id % (BNT/4);
        *(float4*)&Bs[buf][bk][bnq*4] = rb[i];
      }
    }
  };

  gload(0); sstore(0); __syncthreads();

  float acc[8][NB];
  #pragma unroll
  for (int i=0;i<8;i++)
    #pragma unroll
    for (int j=0;j<NB;j++) acc[i][j] = 0.f;

  const int nk = p.K >> 4;
  for (int c=0;c<nk;c++){
    int buf = c&1;
    if (c+1<nk) gload((c+1)<<4);
    #pragma unroll
    for (int ks=0;ks<16;ks++){
      float4 a0 = *(const float4*)&As[buf][ks][ty*4];
      float4 a1 = *(const float4*)&As[buf][ks][64+ty*4];
      float av[8] = {a0.x,a0.y,a0.z,a0.w,a1.x,a1.y,a1.z,a1.w};
      float bv[NB];
      float4 b0 = *(const float4*)&Bs[buf][ks][tx*4];
      bv[0]=b0.x; bv[1]=b0.y; bv[2]=b0.z; bv[3]=b0.w;
      if constexpr (BNT==128){
        float4 b1 = *(const float4*)&Bs[buf][ks][64+tx*4];
        bv[4]=b1.x; bv[5]=b1.y; bv[6]=b1.z; bv[7]=b1.w;
      }
      #pragma unroll
      for (int i=0;i<8;i++)
        #pragma unroll
        for (int j=0;j<NB;j++)
          acc[i][j] = fmaf(av[i], bv[j], acc[i][j]);
    }
    if (c+1<nk){ sstore(buf^1); __syncthreads(); }
  }

  const float* biasp = p.bias ? p.bias + (long long)z*p.biasStride : nullptr;
  const int*   maskp = p.mask ? p.mask + (long long)z*p.maskN : nullptr;
  #pragma unroll
  for (int i=0;i<8;i++){
    int gm = m0 + ((i<4)? (ty*4+i) : (64+ty*4+i-4));
    const float* rgp = p.rg ? p.rg + (long long)(gm/p.rpg)*p.N : nullptr;
    #pragma unroll
    for (int j=0;j<NB;j++){
      int gn = n0 + ((j<4)? (tx*4+j) : (64+tx*4+j-4));
      float v = acc[i][j];
      if (biasp) v += biasp[gn];
      if (rgp)   v += rgp[gn];
      if (p.act==1) v = fmaxf(v, 0.f);
      else if (p.act==2) v = tanhf(v);
      if (maskp && maskp[gn]==0) v = NEGF;
      C[(long long)gm*p.ldc + gn] = v;
    }
  }
}

// small fallback GEMM (used only for cond projection, M=16)
__global__ __launch_bounds__(256) void gemm_small(GemmP p){
  __shared__ float As[16][68], Bs[16][68];
  int z = blockIdx.z;
  const float* A  = p.A  + (long long)(z/p.icA)*p.sAo + (long long)(z%p.icA)*p.sAi;
  const float* Bm = p.Bm + (long long)(z/p.icB)*p.sBo + (long long)(z%p.icB)*p.sBi;
  float* C        = p.C  + (long long)(z/p.icC)*p.sCo + (long long)(z%p.icC)*p.sCi;
  int m0 = blockIdx.y*64, n0 = blockIdx.x*64;
  int tid = threadIdx.x, tx = tid&15, ty = tid>>4;
  float acc[4][4] = {};
  for (int k0=0;k0<p.K;k0+=16){
    #pragma unroll
    for (int i=0;i<4;i++){
      int idx = tid + i*256; int r = idx>>4, c = idx&15;
      int gm = m0+r, gk = k0+c;
      As[c][r] = (gm<p.M && gk<p.K) ? A[(long long)gm*p.lda + gk] : 0.f;
    }
    #pragma unroll
    for (int i=0;i<4;i++){
      int idx = tid + i*256; int c = idx>>6, n = idx&63;
      int gn=n0+n, gk=k0+c;
      Bs[c][n] = (gn<p.N && gk<p.K) ? Bm[(long long)gk*p.ldb + gn] : 0.f;
    }
    __syncthreads();
    #pragma unroll
    for (int k=0;k<16;k++){
      float av[4], bv[4];
      #pragma unroll
      for (int i=0;i<4;i++) av[i] = As[k][ty + 16*i];
      #pragma unroll
      for (int j=0;j<4;j++) bv[j] = Bs[k][tx + 16*j];
      #pragma unroll
      for (int i=0;i<4;i++)
        #pragma unroll
        for (int j=0;j<4;j++) acc[i][j] = fmaf(av[i], bv[j], acc[i][j]);
    }
    __syncthreads();
  }
  #pragma unroll
  for (int i=0;i<4;i++){
    int gm = m0 + ty + 16*i; if (gm >= p.M) continue;
    #pragma unroll
    for (int j=0;j<4;j++){
      int gn = n0 + tx + 16*j; if (gn >= p.N) continue;
      C[(long long)gm*p.ldc + gn] = acc[i][j];
    }
  }
}

// ---------------- positional-encoding table (double, matches numpy) ----------------
__global__ void pe_kernel(float* __restrict__ pe){
  int t = blockIdx.x; int d = threadIdx.x;
  double expo = (double)(2*(d/2)) / 256.0;
  double ang  = (double)t / pow(10000.0, expo);
  pe[t*Dc + d] = (float)(((d&1)==0) ? sin(ang) : cos(ang));
}
__global__ void embed_kernel(const int* __restrict__ text, const float* __restrict__ emb,
                             const float* __restrict__ pe, float* __restrict__ h){
  int row = blockIdx.x; int d = threadIdx.x;
  int t = row % TTc;
  int tok = text[row];
  h[(size_t)row*Dc + d] = emb[(size_t)tok*Dc + d] * 16.0f + pe[t*Dc + d];
}

// ---------------- residual + layernorm ----------------
__global__ void ln_kernel(const float* __restrict__ x, const float* __restrict__ add,
                          const float* __restrict__ g, const float* __restrict__ b,
                          float* __restrict__ out){
  int row = blockIdx.x; int d = threadIdx.x;      // 256 threads
  __shared__ float red[8];
  __shared__ float mean_s, var_s;
  float v = x[(size_t)row*Dc + d] + add[(size_t)row*Dc + d];
  float s = warpSum(v);
  if ((d&31)==0) red[d>>5] = s;
  __syncthreads();
  if (d==0){ float t=0; for (int i=0;i<8;i++) t += red[i]; mean_s = t*(1.f/Dc); }
  __syncthreads();
  float diff = v - mean_s;
  s = warpSum(diff*diff);
  if ((d&31)==0) red[d>>5] = s;
  __syncthreads();
  if (d==0){ float t=0; for (int i=0;i<8;i++) t += red[i]; var_s = t*(1.f/Dc); }
  __syncthreads();
  out[(size_t)row*Dc + d] = g[d]*diff*rsqrtf(var_s + 1e-6f) + b[d];
}

// ---------------- masked softmax over keys (scale 1/8 folded in) ----------------
__global__ void softmax_kernel(float* __restrict__ sc, const int* __restrict__ text){
  int row = blockIdx.x;                      // over B*H*TT
  int b = row / (Hc*TTc);
  float* p = sc + (size_t)row*TTc;
  int tid = threadIdx.x;                     // 128 threads
  __shared__ float red[4];
  __shared__ float mx_s, sum_s;
  float v[4];
  #pragma unroll
  for (int i=0;i<4;i++){
    int j = tid + i*128;
    float s = p[j]*0.125f;
    if (text[b*TTc + j] == 0) s += NEGF;
    v[i] = s;
  }
  float m = fmaxf(fmaxf(v[0],v[1]), fmaxf(v[2],v[3]));
  m = warpMax(m);
  if ((tid&31)==0) red[tid>>5] = m;
  __syncthreads();
  if (tid==0) mx_s = fmaxf(fmaxf(red[0],red[1]), fmaxf(red[2],red[3]));
  __syncthreads();
  float mx = mx_s, s = 0.f;
  #pragma unroll
  for (int i=0;i<4;i++){ v[i] = expf(v[i]-mx); s += v[i]; }
  s = warpSum(s);
  if ((tid&31)==0) red[tid>>5] = s;
  __syncthreads();
  if (tid==0) sum_s = red[0]+red[1]+red[2]+red[3];
  __syncthreads();
  float inv = 1.f/sum_s;
  #pragma unroll
  for (int i=0;i<4;i++) p[tid + i*128] = v[i]*inv;
}

// ---------------- wext / constant-term prep for logp ----------------
__global__ void prep_kernel(const float* __restrict__ mu, const float* __restrict__ lv,
                            float* __restrict__ wext, float* __restrict__ cb){
  int row = blockIdx.x; int d = threadIdx.x;    // 256 threads
  __shared__ float red[8];
  float l = lv[(size_t)row*Dc + d];
  float m = mu[(size_t)row*Dc + d];
  float spr = expf(-l);
  wext[(size_t)row*2*Dc + d]      = -0.5f*spr;
  wext[(size_t)row*2*Dc + Dc + d] = m*spr;
  float contrib = -0.5f*1.8378770664093453f - 0.5f*l - 0.5f*m*m*spr;
  float s = warpSum(contrib);
  if ((d&31)==0) red[d>>5] = s;
  __syncthreads();
  if (d==0){ float t=0; for (int i=0;i<8;i++) t += red[i]; cb[row] = t; }
}

// ---------------- [zc^2, zc] feature build ----------------
__global__ void xext_kernel(const float* __restrict__ zc, float* __restrict__ xe){
  size_t idx = (size_t)blockIdx.x*256 + threadIdx.x;
  size_t row = idx >> 8; int d = (int)(idx & 255);
  float z = zc[idx];
  xe[row*512 + d]       = z*z;
  xe[row*512 + 256 + d] = z;
}

// ---------------- flow coupling update ----------------
__global__ void flowupd_kernel(const float* __restrict__ src, const float* __restrict__ m,
                               float* __restrict__ dst){
  size_t idx = (size_t)blockIdx.x*128 + threadIdx.x;
  size_t row = idx >> 7; int c = (int)(idx & 127);
  dst[row*256 + c]       = src[row*256 + 128 + c] + m[row*128 + c];
  dst[row*256 + 128 + c] = src[row*256 + c];
}

// ---------------- MAS forward DP (ballot-packed choices) ----------------
__global__ void mas_fwd(const float* __restrict__ logp, unsigned int* __restrict__ chp){
  int b = blockIdx.x, j = threadIdx.x;            // 512 threads
  __shared__ float Q[2][TTc];
  const float* lp = logp + (size_t)b*TZc*TTc;
  Q[0][j] = (j==0) ? lp[j] : NEGF;
  __syncthreads();
  int cur = 0;
  float nxt = lp[TTc + j];
  for (int t=1; t<TZc; t++){
    float qj = Q[cur][j];
    float qm = (j>0) ? Q[cur][j-1] : NEGF;
    unsigned bal = __ballot_sync(0xffffffffu, qm > qj);
    if ((j&31)==0) chp[((size_t)b*(TZc-1) + (t-1))*16 + (j>>5)] = bal;
    float val = nxt + fmaxf(qj, qm);
    if (t+1 < TZc) nxt = lp[(size_t)(t+1)*TTc + j];
    Q[cur^1][j] = val;
    cur ^= 1;
    __syncthreads();
  }
}

// ---------------- MAS backtrack (8-step batched loads) ----------------
__global__ void mas_bwd(const unsigned int* __restrict__ chp, const int* __restrict__ text,
                        int* __restrict__ path){
  int b = blockIdx.x; int tid = threadIdx.x;       // 512 threads
  __shared__ int red[16];
  int m = (text[b*TTc + tid] != 0) ? 1 : 0;
  #pragma unroll
  for (int o=16;o;o>>=1) m += __shfl_xor_sync(0xffffffffu, m, o);
  if ((tid&31)==0) red[tid>>5] = m;
  __syncthreads();
  if (tid==0){
    int s = 0; for (int i=0;i<16;i++) s += red[i];
    int j = s - 1;
    path[b*TZc + TZc-1] = j;
    const unsigned int* cp_ = chp + (size_t)b*(TZc-1)*16;
    int t = TZc-2;
    while (t >= 0){
      int w0 = j>>5;
      unsigned wa[8], wb[8];
      #pragma unroll
      for (int i=0;i<8;i++){
        int tt = t - i;
        if (tt >= 0){
          wa[i] = __ldg(&cp_[(size_t)tt*16 + w0]);
          wb[i] = (w0>0) ? __ldg(&cp_[(size_t)tt*16 + w0-1]) : 0u;
        }
      }
      #pragma unroll
      for (int i=0;i<8;i++){
        int tt = t - i;
        if (tt >= 0){
          unsigned word = ((j>>5)==w0) ? wa[i] : wb[i];
          j -= (int)((word >> (j&31)) & 1u);
          path[b*TZc + tt] = j;
        }
      }
      t -= 8;
    }
  }
}

// ---------------- outputs ----------------
__global__ void ctx_kernel(const float* __restrict__ mu, const int* __restrict__ path,
                           float* __restrict__ out){
  int row = blockIdx.x; int d = threadIdx.x;
  int b = row / TZc;
  int j = path[row];
  out[(size_t)row*Dc + d] = mu[((size_t)b*TTc + j)*Dc + d];
}
__global__ void hcopy_kernel(const float* __restrict__ h, float* __restrict__ out){
  size_t idx = (size_t)blockIdx.x*256 + threadIdx.x;
  out[idx] = h[idx];
}

// ---------------- host orchestration ----------------
static GemmP mk(const float*A,int lda,long long sAo,long long sAi,int icA,
                const float*Bm,int ldb,long long sBo,long long sBi,int icB,
                float*C,int ldc,long long sCo,long long sCi,int icC,
                const float*bias,long long bs,const float*rg,int rpg,
                const int*mask,int maskN,int M,int N,int K,int act)
{
  GemmP p;
  p.A=A; p.lda=lda; p.sAo=sAo; p.sAi=sAi; p.icA=(icA>0?icA:1);
  p.Bm=Bm; p.ldb=ldb; p.sBo=sBo; p.sBi=sBi; p.icB=(icB>0?icB:1);
  p.C=C; p.ldc=ldc; p.sCo=sCo; p.sCi=sCi; p.icC=(icC>0?icC:1);
  p.bias=bias; p.biasStride=bs; p.rg=rg; p.rpg=(rpg>0?rpg:1);
  p.mask=mask; p.maskN=maskN;
  p.M=M; p.N=N; p.K=K; p.act=act;
  return p;
}

static void launch_sg(const GemmP& p, int batch, int BNT, int TB, int CONV){
  dim3 grid(p.N/BNT, p.M/128, batch);
  if (CONV)          sgemm_kernel<128,0,1><<<grid,256>>>(p);
  else if (BNT==64)  sgemm_kernel<64 ,0,0><<<grid,256>>>(p);
  else if (TB)       sgemm_kernel<128,1,0><<<grid,256>>>(p);
  else               sgemm_kernel<128,0,0><<<grid,256>>>(p);
}

extern "C" void kernel_launch(void* const* d_in, const int* in_sizes, int n_in,
                              void* d_out, int out_size){
  (void)in_sizes; (void)n_in; (void)out_size;
  const float* z     = (const float*)d_in[0];
  const int*   text  = (const int*)  d_in[1];
  const float* cond  = (const float*)d_in[2];
  const float* emb   = (const float*)d_in[3];
  const float* wq    = (const float*)d_in[4];
  const float* wk    = (const float*)d_in[5];
  const float* wv    = (const float*)d_in[6];
  const float* wo    = (const float*)d_in[7];
  const float* bq    = (const float*)d_in[8];
  const float* bk    = (const float*)d_in[9];
  const float* bv    = (const float*)d_in[10];
  const float* bo    = (const float*)d_in[11];
  const float* ln1g  = (const float*)d_in[12];
  const float* ln1b  = (const float*)d_in[13];
  const float* ln2g  = (const float*)d_in[14];
  const float* ln2b  = (const float*)d_in[15];
  const float* w1    = (const float*)d_in[16];
  const float* b1    = (const float*)d_in[17];
  const float* w2    = (const float*)d_in[18];
  const float* b2    = (const float*)d_in[19];
  const float* mu_w  = (const float*)d_in[20];
  const float* mu_b  = (const float*)d_in[21];
  const float* lv_w  = (const float*)d_in[22];
  const float* lv_b  = (const float*)d_in[23];
  const float* f_in  = (const float*)d_in[24];
  const float* f_inb = (const float*)d_in[25];
  const float* f_cd  = (const float*)d_in[26];
  const float* f_cv  = (const float*)d_in[27];
  const float* f_cvb = (const float*)d_in[28];
  const float* f_out = (const float*)d_in[29];
  const float* f_outb= (const float*)d_in[30];
  float* out = (float*)d_out;

  float *h,*q,*k,*v,*ao,*t1,*ffn,*sc,*mu,*lv,*wext,*cb,*zca,*zcb,*hh,*hh2,*mm,*cp,*xe,*pe,*lp;
  unsigned int* chp; int* path;
  cudaGetSymbolAddress((void**)&h,  g_h);
  cudaGetSymbolAddress((void**)&q,  g_q);
  cudaGetSymbolAddress((void**)&k,  g_k);
  cudaGetSymbolAddress((void**)&v,  g_v);
  cudaGetSymbolAddress((void**)&ao, g_ao);
  cudaGetSymbolAddress((void**)&t1, g_t1);
  cudaGetSymbolAddress((void**)&ffn,g_ffn);
  cudaGetSymbolAddress((void**)&sc, g_sc);
  cudaGetSymbolAddress((void**)&mu, g_mu);
  cudaGetSymbolAddress((void**)&lv, g_lv);
  cudaGetSymbolAddress((void**)&wext,g_wext);
  cudaGetSymbolAddress((void**)&cb, g_cb);
  cudaGetSymbolAddress((void**)&zca,g_zca);
  cudaGetSymbolAddress((void**)&zcb,g_zcb);
  cudaGetSymbolAddress((void**)&hh, g_hh);
  cudaGetSymbolAddress((void**)&hh2,g_hh2);
  cudaGetSymbolAddress((void**)&mm, g_m);
  cudaGetSymbolAddress((void**)&cp, g_cp);
  cudaGetSymbolAddress((void**)&xe, g_xe);
  cudaGetSymbolAddress((void**)&pe, g_pe);
  cudaGetSymbolAddress((void**)&lp, g_logp);
  cudaGetSymbolAddress((void**)&chp, g_chp);
  cudaGetSymbolAddress((void**)&path, g_path);

  const int MROWS = Bc*TTc;           // 8192
  const int MZ    = Bc*TZc;           // 32768

  // ---- text encoder ----
  pe_kernel<<<TTc, 256>>>(pe);
  embed_kernel<<<MROWS, 256>>>(text, emb, pe, h);
  for (int l=0; l<Lc; l++){
    const float* Wq = wq + (size_t)l*Dc*Dc;  const float* Bq = bq + (size_t)l*Dc;
    const float* Wk = wk + (size_t)l*Dc*Dc;  const float* Bk = bk + (size_t)l*Dc;
    const float* Wv = wv + (size_t)l*Dc*Dc;  const float* Bv = bv + (size_t)l*Dc;
    const float* Wo = wo + (size_t)l*Dc*Dc;  const float* Bo = bo + (size_t)l*Dc;
    launch_sg(mk(h,Dc,0,0,1,  Wq,Dc,0,0,1, q,Dc,0,0,1, Bq,0, nullptr,0, nullptr,0, MROWS,Dc,Dc,0), 1, 128,0,0);
    launch_sg(mk(h,Dc,0,0,1,  Wk,Dc,0,0,1, k,Dc,0,0,1, Bk,0, nullptr,0, nullptr,0, MROWS,Dc,Dc,0), 1, 128,0,0);
    launch_sg(mk(h,Dc,0,0,1,  Wv,Dc,0,0,1, v,Dc,0,0,1, Bv,0, nullptr,0, nullptr,0, MROWS,Dc,Dc,0), 1, 128,0,0);
    // scores[b,h] = q @ k^T
    launch_sg(mk(q,Dc,(long long)TTc*Dc,DHc,Hc,
                 k,Dc,(long long)TTc*Dc,DHc,Hc,
                 sc,TTc,(long long)TTc*TTc,0,1,
                 nullptr,0, nullptr,0, nullptr,0, TTc,TTc,DHc,0), Bc*Hc, 128,1,0);
    softmax_kernel<<<Bc*Hc*TTc, 128>>>(sc, text);
    // out[b,h] = attn @ v
    launch_sg(mk(sc,TTc,(long long)TTc*TTc,0,1,
                 v,Dc,(long long)TTc*Dc,DHc,Hc,
                 ao,Dc,(long long)TTc*Dc,DHc,Hc,
                 nullptr,0, nullptr,0, nullptr,0, TTc,DHc,TTc,0), Bc*Hc, 64,0,0);
    launch_sg(mk(ao,Dc,0,0,1, Wo,Dc,0,0,1, t1,Dc,0,0,1, Bo,0, nullptr,0, nullptr,0, MROWS,Dc,Dc,0), 1, 128,0,0);
    ln_kernel<<<MROWS, 256>>>(h, t1, ln1g + (size_t)l*Dc, ln1b + (size_t)l*Dc, h);
    launch_sg(mk(h,Dc,0,0,1, w1+(size_t)l*Dc*DFFc,DFFc,0,0,1, ffn,DFFc,0,0,1,
                 b1+(size_t)l*DFFc,0, nullptr,0, nullptr,0, MROWS,DFFc,Dc,1), 1, 128,0,0);
    launch_sg(mk(ffn,DFFc,0,0,1, w2+(size_t)l*DFFc*Dc,Dc,0,0,1, t1,Dc,0,0,1,
                 b2+(size_t)l*Dc,0, nullptr,0, nullptr,0, MROWS,Dc,DFFc,0), 1, 128,0,0);
    ln_kernel<<<MROWS, 256>>>(h, t1, ln2g + (size_t)l*Dc, ln2b + (size_t)l*Dc, h);
  }

  // ---- mu / logvar / logp weights ----
  launch_sg(mk(h,Dc,0,0,1, mu_w,Dc,0,0,1, mu,Dc,0,0,1, mu_b,0, nullptr,0, nullptr,0, MROWS,Dc,Dc,0), 1, 128,0,0);
  launch_sg(mk(h,Dc,0,0,1, lv_w,Dc,0,0,1, lv,Dc,0,0,1, lv_b,0, nullptr,0, nullptr,0, MROWS,Dc,Dc,0), 1, 128,0,0);
  prep_kernel<<<MROWS, 256>>>(mu, lv, wext, cb);

  // ---- flows ----
  cudaMemcpyAsync(zca, z, (size_t)Bc*TZc*CHc*sizeof(float), cudaMemcpyDeviceToDevice);
  for (int f=0; f<FLOWSc; f++){
    float* src = (f&1) ? zcb : zca;
    float* dst = (f&1) ? zca : zcb;
    // cond projection (16 x 256) — small kernel
    {
      GemmP p = mk(cond,Gc,0,0,1, f_cd + (size_t)f*Gc*HIDc,HIDc,0,0,1,
                   cp,HIDc,0,0,1, nullptr,0, nullptr,0, nullptr,0, Bc,HIDc,Gc,0);
      dim3 grid((HIDc+63)/64, 1, 1);
      gemm_small<<<grid,256>>>(p);
    }
    // hh = x0 @ flow_in + b + condproj[b]
    launch_sg(mk(src,CHc,0,0,1,
                 f_in + (size_t)f*(CHc/2)*HIDc, HIDc,0,0,1,
                 hh,HIDc,0,0,1,
                 f_inb + (size_t)f*HIDc, 0,
                 cp, TZc,
                 nullptr,0, MZ, HIDc, CHc/2, 0), 1, 128,0,0);
    // conv (K=5, SAME, per-batch zero pad) + tanh
    launch_sg(mk(hh,HIDc,0,0,1,
                 f_cv + (size_t)f*KTAP*HIDc*HIDc, HIDc,0,0,1,
                 hh2,HIDc,0,0,1,
                 f_cvb + (size_t)f*HIDc, 0,
                 nullptr,0, nullptr,0, MZ, HIDc, KTAP*HIDc, 2), 1, 128,0,1);
    // m = hh2 @ flow_out + b
    launch_sg(mk(hh2,HIDc,0,0,1,
                 f_out + (size_t)f*HIDc*(CHc/2), CHc/2,0,0,1,
                 mm,CHc/2,0,0,1,
                 f_outb + (size_t)f*(CHc/2), 0,
                 nullptr,0, nullptr,0, MZ, CHc/2, HIDc, 0), 1, 128,0,0);
    // zc' = [x1 + m, x0]
    flowupd_kernel<<<(MZ*(CHc/2))/128, 128>>>(src, mm, dst);
  }
  // FLOWS=4 -> final zc in zca

  // ---- logp = [zc^2, zc] @ wext^T + c, masked ----
  xext_kernel<<<(MZ*CHc)/256, 256>>>(zca, xe);
  launch_sg(mk(xe,2*Dc,(long long)TZc*2*Dc,0,1,
               wext,2*Dc,(long long)TTc*2*Dc,0,1,
               lp,TTc,(long long)TZc*TTc,0,1,
               cb, TTc,
               nullptr,0,
               text, TTc,
               TZc, TTc, 2*Dc, 0), Bc, 128,1,0);

  // ---- MAS path + outputs ----
  mas_fwd<<<Bc, TTc>>>(lp, chp);
  mas_bwd<<<Bc, TTc>>>(chp, text, path);
  ctx_kernel<<<Bc*TZc, 256>>>(mu, path, out);
  hcopy_kernel<<<(Bc*TTc*Dc)/256, 256>>>(h, out + (size_t)Bc*TZc*Dc);
}